// round 1
// baseline (speedup 1.0000x reference)
#include <cuda_runtime.h>
#include <cuda_bf16.h>

// Causal MHA: B=2, H=16, S=2048, DK=64, fp32.
// Flash-attention style: one CTA per (batch*head, 64-query tile).
// 256 threads; each thread owns a 4x4 fragment of the 64x64 score tile
// and a 4x4 fragment of the 64x64 output tile.

#define S_LEN 2048
#define DH    64
#define BM    64
#define BN    64
#define LD    68   // smem row stride (floats); 4-float pad, 16B aligned

__global__ void __launch_bounds__(256)
fa_causal_kernel(const float* __restrict__ Q,
                 const float* __restrict__ K,
                 const float* __restrict__ V,
                 float* __restrict__ O)
{
    extern __shared__ float sm[];
    float* sQ = sm;                 // [BM][LD]
    float* sK = sm + BM * LD;       // [BN][LD]
    float* sV = sK + BN * LD;       // [BN][LD]
    float* sP = sK;                 // P tile reuses K buffer

    const int qt  = blockIdx.x;         // query tile 0..31
    const int bh  = blockIdx.y;         // 0..31
    const int tid = threadIdx.x;
    const int tr  = tid >> 4;           // 0..15 -> rows tr*4 .. tr*4+3
    const int tc  = tid & 15;           // 0..15

    const float* Qg = Q + ((long)bh * S_LEN + (long)qt * BM) * DH;
    const float* Kg = K + (long)bh * S_LEN * DH;
    const float* Vg = V + (long)bh * S_LEN * DH;

    // ---- load Q tile, folding in the 1/sqrt(dk) scale ----
    const float scale = 0.125f;  // 1/sqrt(64)
    #pragma unroll
    for (int i = tid; i < BM * DH / 4; i += 256) {
        int r = (i * 4) / DH, c = (i * 4) % DH;
        float4 v = *(const float4*)(Qg + r * DH + c);
        v.x *= scale; v.y *= scale; v.z *= scale; v.w *= scale;
        *(float4*)(sQ + r * LD + c) = v;
    }

    float accO[4][4];
    float mrow[4], lrow[4];
    #pragma unroll
    for (int r = 0; r < 4; r++) {
        mrow[r] = -1e30f; lrow[r] = 0.f;
        #pragma unroll
        for (int c = 0; c < 4; c++) accO[r][c] = 0.f;
    }

    for (int kb = 0; kb <= qt; ++kb) {
        // ---- load K,V tiles ----
        const float* Kt = Kg + (long)kb * BN * DH;
        const float* Vt = Vg + (long)kb * BN * DH;
        __syncthreads();   // previous iter done reading sK(=sP)/sV; also covers sQ on iter 0
        #pragma unroll
        for (int i = tid; i < BN * DH / 4; i += 256) {
            int r = (i * 4) / DH, c = (i * 4) % DH;
            *(float4*)(sK + r * LD + c) = *(const float4*)(Kt + r * DH + c);
            *(float4*)(sV + r * LD + c) = *(const float4*)(Vt + r * DH + c);
        }
        __syncthreads();

        // ---- GEMM1: s[r][c] = sum_k sQ[tr*4+r][k] * sK[tc+16c][k] ----
        float s[4][4];
        #pragma unroll
        for (int r = 0; r < 4; r++)
            #pragma unroll
            for (int c = 0; c < 4; c++) s[r][c] = 0.f;

        #pragma unroll 4
        for (int kk = 0; kk < DH; kk += 4) {
            float4 qf[4], kf[4];
            #pragma unroll
            for (int r = 0; r < 4; r++) qf[r] = *(const float4*)(sQ + (tr * 4 + r) * LD + kk);
            #pragma unroll
            for (int c = 0; c < 4; c++) kf[c] = *(const float4*)(sK + (tc + 16 * c) * LD + kk);
            #pragma unroll
            for (int r = 0; r < 4; r++)
                #pragma unroll
                for (int c = 0; c < 4; c++) {
                    s[r][c] = fmaf(qf[r].x, kf[c].x, s[r][c]);
                    s[r][c] = fmaf(qf[r].y, kf[c].y, s[r][c]);
                    s[r][c] = fmaf(qf[r].z, kf[c].z, s[r][c]);
                    s[r][c] = fmaf(qf[r].w, kf[c].w, s[r][c]);
                }
        }

        // ---- causal mask on the diagonal tile ----
        if (kb == qt) {
            #pragma unroll
            for (int r = 0; r < 4; r++) {
                int i = tr * 4 + r;
                #pragma unroll
                for (int c = 0; c < 4; c++) {
                    int j = tc + 16 * c;
                    if (j > i) s[r][c] = -1e30f;
                }
            }
        }

        // ---- online softmax update ----
        float p[4][4];
        #pragma unroll
        for (int r = 0; r < 4; r++) {
            float mx = s[r][0];
            #pragma unroll
            for (int c = 1; c < 4; c++) mx = fmaxf(mx, s[r][c]);
            // reduce across the 16 lanes sharing this row (lane%16 groups)
            #pragma unroll
            for (int o = 8; o >= 1; o >>= 1)
                mx = fmaxf(mx, __shfl_xor_sync(0xffffffffu, mx, o));
            float mnew  = fmaxf(mrow[r], mx);
            float alpha = __expf(mrow[r] - mnew);
            float ps = 0.f;
            #pragma unroll
            for (int c = 0; c < 4; c++) {
                p[r][c] = __expf(s[r][c] - mnew);
                ps += p[r][c];
            }
            #pragma unroll
            for (int o = 8; o >= 1; o >>= 1)
                ps += __shfl_xor_sync(0xffffffffu, ps, o);
            lrow[r] = lrow[r] * alpha + ps;
            mrow[r] = mnew;
            #pragma unroll
            for (int c = 0; c < 4; c++) accO[r][c] *= alpha;
        }

        // ---- stage P into smem (reuses K buffer) ----
        __syncthreads();   // all warps done reading sK
        #pragma unroll
        for (int r = 0; r < 4; r++)
            #pragma unroll
            for (int c = 0; c < 4; c++)
                sP[(tr * 4 + r) * LD + tc + 16 * c] = p[r][c];
        __syncthreads();

        // ---- GEMM2: accO[r][c] += sum_j sP[tr*4+r][j] * sV[j][tc*4+c] ----
        #pragma unroll 4
        for (int kk = 0; kk < BN; kk += 4) {
            float4 pf[4], vf[4];
            #pragma unroll
            for (int r = 0; r < 4; r++) pf[r] = *(const float4*)(sP + (tr * 4 + r) * LD + kk);
            #pragma unroll
            for (int j = 0; j < 4; j++) vf[j] = *(const float4*)(sV + (kk + j) * LD + tc * 4);
            #pragma unroll
            for (int r = 0; r < 4; r++) {
                float pr[4] = {pf[r].x, pf[r].y, pf[r].z, pf[r].w};
                #pragma unroll
                for (int j = 0; j < 4; j++) {
                    accO[r][0] = fmaf(pr[j], vf[j].x, accO[r][0]);
                    accO[r][1] = fmaf(pr[j], vf[j].y, accO[r][1]);
                    accO[r][2] = fmaf(pr[j], vf[j].z, accO[r][2]);
                    accO[r][3] = fmaf(pr[j], vf[j].w, accO[r][3]);
                }
            }
        }
    }

    // ---- epilogue: normalize and store ----
    float* Og = O + ((long)bh * S_LEN + (long)qt * BM) * DH;
    #pragma unroll
    for (int r = 0; r < 4; r++) {
        float inv = 1.f / lrow[r];
        float4 o;
        o.x = accO[r][0] * inv;
        o.y = accO[r][1] * inv;
        o.z = accO[r][2] * inv;
        o.w = accO[r][3] * inv;
        *(float4*)(Og + (tr * 4 + r) * DH + tc * 4) = o;
    }
}

extern "C" void kernel_launch(void* const* d_in, const int* in_sizes, int n_in,
                              void* d_out, int out_size)
{
    // Inputs (metadata order): d_model, num_heads, Q, K, V, mask.
    // Locate Q,K,V robustly as the first three inputs of B*H*S*DK elements.
    const int QKV_ELEMS = 2 * 16 * 2048 * 64;
    const float* qkv[3] = {nullptr, nullptr, nullptr};
    int found = 0;
    for (int i = 0; i < n_in && found < 3; ++i) {
        if (in_sizes[i] == QKV_ELEMS) qkv[found++] = (const float*)d_in[i];
    }
    const float* Q = qkv[0];
    const float* K = qkv[1];
    const float* V = qkv[2];
    float* O = (float*)d_out;

    const int smem_bytes = 3 * BM * LD * (int)sizeof(float);  // 52224
    static bool attr_set = false;
    if (!attr_set) {
        cudaFuncSetAttribute(fa_causal_kernel,
                             cudaFuncAttributeMaxDynamicSharedMemorySize, smem_bytes);
        attr_set = true;
    }

    dim3 grid(S_LEN / BM, 2 * 16);   // (32 q-tiles, 32 batch*heads)
    fa_causal_kernel<<<grid, 256, smem_bytes>>>(Q, K, V, O);
}